// round 1
// baseline (speedup 1.0000x reference)
#include <cuda_runtime.h>
#include <cuda_bf16.h>

// Problem constants (fixed shapes per reference)
#define NN 100000
#define EE 3200000
#define DD 64
#define NB_SCAN ((NN + 255) / 256)   // 391 blocks for scan

// ---------------- static device scratch (no runtime allocation) ----------------
static __device__ int   g_outcnt[NN];
static __device__ int   g_incnt[NN];
static __device__ float g_outnorm[NN];
static __device__ float g_innorm[NN];
static __device__ int   g_rowptr[NN + 1];
static __device__ int   g_cursor[NN];
static __device__ int   g_col[EE + NN];
static __device__ float g_s[NN * DD];     // scaled features (input to SpMM)
static __device__ float g_agg[NN * DD];   // aggregation output
static __device__ int   g_bsums[512];     // scan block sums

// ---------------- kernels ----------------

__global__ void k_zero() {
    int n = blockIdx.x * blockDim.x + threadIdx.x;
    if (n < NN) { g_outcnt[n] = 0; g_incnt[n] = 0; }
}

__global__ void k_degree(const int* __restrict__ src, const int* __restrict__ dst) {
    int e = blockIdx.x * blockDim.x + threadIdx.x;
    if (e < EE) {
        atomicAdd(&g_outcnt[src[e]], 1);
        atomicAdd(&g_incnt[dst[e]], 1);
    }
}

__global__ void k_norm() {
    int n = blockIdx.x * blockDim.x + threadIdx.x;
    if (n < NN) {
        g_outnorm[n] = rsqrtf((float)(g_outcnt[n] + 1));  // +1 self loop, always >=1
        g_innorm[n]  = rsqrtf((float)(g_incnt[n] + 1));
    }
}

// --- exclusive scan of deg[] = incnt[]+1 into rowptr ---
__global__ void k_scan1() {
    __shared__ int s[256];
    int t = threadIdx.x;
    int n = blockIdx.x * 256 + t;
    int v = (n < NN) ? (g_incnt[n] + 1) : 0;
    s[t] = v;
    __syncthreads();
    for (int off = 1; off < 256; off <<= 1) {
        int tmp = (t >= off) ? s[t - off] : 0;
        __syncthreads();
        s[t] += tmp;
        __syncthreads();
    }
    if (t == 255) g_bsums[blockIdx.x] = s[255];
}

__global__ void k_scan2() {
    __shared__ int s[512];
    int t = threadIdx.x;
    int v = (t < NB_SCAN) ? g_bsums[t] : 0;
    s[t] = v;
    __syncthreads();
    for (int off = 1; off < 512; off <<= 1) {
        int tmp = (t >= off) ? s[t - off] : 0;
        __syncthreads();
        s[t] += tmp;
        __syncthreads();
    }
    if (t < NB_SCAN) g_bsums[t] = s[t] - v;   // exclusive block offsets
}

__global__ void k_scan3() {
    __shared__ int s[256];
    int t = threadIdx.x;
    int n = blockIdx.x * 256 + t;
    int v = (n < NN) ? (g_incnt[n] + 1) : 0;
    s[t] = v;
    __syncthreads();
    for (int off = 1; off < 256; off <<= 1) {
        int tmp = (t >= off) ? s[t - off] : 0;
        __syncthreads();
        s[t] += tmp;
        __syncthreads();
    }
    if (n < NN) {
        int start = g_bsums[blockIdx.x] + s[t] - v;   // exclusive scan result
        g_rowptr[n] = start;
        g_cursor[n] = start;
    }
    if (blockIdx.x == 0 && t == 0) g_rowptr[NN] = EE + NN;
}

__global__ void k_fill(const int* __restrict__ src, const int* __restrict__ dst) {
    int i = blockIdx.x * blockDim.x + threadIdx.x;
    if (i < EE + NN) {
        int s, d;
        if (i < EE) { s = src[i]; d = dst[i]; }
        else        { s = i - EE; d = s; }        // self loops
        int pos = atomicAdd(&g_cursor[d], 1);
        g_col[pos] = s;
    }
}

// s0 = (weight[n] * W_in + b_in) * out_norm[n]
__global__ void k_input(const float* __restrict__ weight,
                        const float* __restrict__ Win,
                        const float* __restrict__ bin) {
    int idx = blockIdx.x * blockDim.x + threadIdx.x;   // over NN*16 float4 groups
    if (idx < NN * 16) {
        int n = idx >> 4;
        int j = (idx & 15) * 4;
        float w = weight[n];
        float on = g_outnorm[n];
        float4 o;
        o.x = (w * Win[j + 0] + bin[j + 0]) * on;
        o.y = (w * Win[j + 1] + bin[j + 1]) * on;
        o.z = (w * Win[j + 2] + bin[j + 2]) * on;
        o.w = (w * Win[j + 3] + bin[j + 3]) * on;
        *reinterpret_cast<float4*>(&g_s[n * DD + j]) = o;
    }
}

// warp-per-node pull aggregation: agg[n] = sum over in-edges of s[src]
__global__ void k_spmm() {
    int gtid = blockIdx.x * blockDim.x + threadIdx.x;
    int n = gtid >> 5;
    int lane = gtid & 31;
    if (n >= NN) return;
    int beg = g_rowptr[n];
    int end = g_rowptr[n + 1];
    const float2* sp = reinterpret_cast<const float2*>(g_s);
    float2 acc = make_float2(0.f, 0.f);
    for (int e = beg; e < end; e += 32) {
        int cnt = min(32, end - e);
        int idx = (lane < cnt) ? g_col[e + lane] : 0;
        #pragma unroll 4
        for (int j = 0; j < cnt; j++) {
            int srcn = __shfl_sync(0xffffffffu, idx, j);
            float2 v = sp[srcn * 32 + lane];
            acc.x += v.x;
            acc.y += v.y;
        }
    }
    reinterpret_cast<float2*>(g_agg)[n * 32 + lane] = acc;
}

// fused dense: x = agg[n]*in_norm; y = x@W + b; then either
//   (non-final) s[n] = leaky(y) * out_norm[n]
//   (final)     out[n] = y @ Wp + bp
__global__ void k_dense(const float* __restrict__ W,
                        const float* __restrict__ b,
                        int final_flag,
                        const float* __restrict__ Wp,
                        const float* __restrict__ bp,
                        float* __restrict__ out) {
    __shared__ float Ws[DD * DD];
    __shared__ float Bs[DD];
    __shared__ float Wps[DD];
    int t = threadIdx.x;
    {
        const float4* w4 = reinterpret_cast<const float4*>(W);
        float4* s4 = reinterpret_cast<float4*>(Ws);
        #pragma unroll
        for (int i = 0; i < 8; i++) s4[t + i * 128] = w4[t + i * 128];
        if (t < DD) { Bs[t] = b[t]; Wps[t] = Wp[t]; }
    }
    __syncthreads();

    int n = blockIdx.x * blockDim.x + t;
    if (n >= NN) return;

    float x[DD];
    {
        float sc = g_innorm[n];
        const float4* ap = reinterpret_cast<const float4*>(&g_agg[n * DD]);
        #pragma unroll
        for (int i = 0; i < 16; i++) {
            float4 v = ap[i];
            x[i * 4 + 0] = v.x * sc;
            x[i * 4 + 1] = v.y * sc;
            x[i * 4 + 2] = v.z * sc;
            x[i * 4 + 3] = v.w * sc;
        }
    }

    float on = g_outnorm[n];
    float pred = 0.f;
    #pragma unroll
    for (int c = 0; c < 4; c++) {
        float acc[16];
        #pragma unroll
        for (int o = 0; o < 16; o++) acc[o] = Bs[c * 16 + o];
        #pragma unroll
        for (int k = 0; k < DD; k++) {
            float xv = x[k];
            const float4* wr = reinterpret_cast<const float4*>(&Ws[k * DD + c * 16]);
            float4 w0 = wr[0], w1 = wr[1], w2 = wr[2], w3 = wr[3];
            acc[0]  += xv * w0.x;  acc[1]  += xv * w0.y;
            acc[2]  += xv * w0.z;  acc[3]  += xv * w0.w;
            acc[4]  += xv * w1.x;  acc[5]  += xv * w1.y;
            acc[6]  += xv * w1.z;  acc[7]  += xv * w1.w;
            acc[8]  += xv * w2.x;  acc[9]  += xv * w2.y;
            acc[10] += xv * w2.z;  acc[11] += xv * w2.w;
            acc[12] += xv * w3.x;  acc[13] += xv * w3.y;
            acc[14] += xv * w3.z;  acc[15] += xv * w3.w;
        }
        if (!final_flag) {
            #pragma unroll
            for (int o = 0; o < 16; o++) {
                float y = acc[o];
                y = (y > 0.f) ? y : 0.01f * y;
                acc[o] = y * on;
            }
            float4* op = reinterpret_cast<float4*>(&g_s[n * DD + c * 16]);
            op[0] = make_float4(acc[0],  acc[1],  acc[2],  acc[3]);
            op[1] = make_float4(acc[4],  acc[5],  acc[6],  acc[7]);
            op[2] = make_float4(acc[8],  acc[9],  acc[10], acc[11]);
            op[3] = make_float4(acc[12], acc[13], acc[14], acc[15]);
        } else {
            #pragma unroll
            for (int o = 0; o < 16; o++) pred += acc[o] * Wps[c * 16 + o];
        }
    }
    if (final_flag) out[n] = pred + bp[0];
}

extern "C" void kernel_launch(void* const* d_in, const int* in_sizes, int n_in,
                              void* d_out, int out_size) {
    const float* weight = (const float*)d_in[0];
    const int*   src    = (const int*)d_in[1];
    const int*   dst    = (const int*)d_in[2];
    const float* W_in   = (const float*)d_in[3];
    const float* b_in   = (const float*)d_in[4];
    const float* Wc     = (const float*)d_in[5];   // [3,64,64]
    const float* bc     = (const float*)d_in[6];   // [3,64]
    const float* W_pred = (const float*)d_in[7];   // [64]
    const float* b_pred = (const float*)d_in[8];   // [1]
    float* out = (float*)d_out;

    const int TB = 256;
    k_zero<<<(NN + TB - 1) / TB, TB>>>();
    k_degree<<<(EE + TB - 1) / TB, TB>>>(src, dst);
    k_norm<<<(NN + TB - 1) / TB, TB>>>();
    k_scan1<<<NB_SCAN, 256>>>();
    k_scan2<<<1, 512>>>();
    k_scan3<<<NB_SCAN, 256>>>();
    k_fill<<<(EE + NN + TB - 1) / TB, TB>>>(src, dst);
    k_input<<<(NN * 16 + TB - 1) / TB, TB>>>(weight, W_in, b_in);

    int spmm_blocks = (NN * 32 + TB - 1) / TB;
    int dense_blocks = (NN + 127) / 128;
    for (int layer = 0; layer < 3; layer++) {
        k_spmm<<<spmm_blocks, TB>>>();
        int fin = (layer == 2) ? 1 : 0;
        k_dense<<<dense_blocks, 128>>>(Wc + layer * DD * DD, bc + layer * DD,
                                       fin, W_pred, b_pred, out);
    }
}

// round 2
// speedup vs baseline: 1.2976x; 1.2976x over previous
#include <cuda_runtime.h>
#include <cuda_fp16.h>

// Problem constants (fixed shapes per reference)
#define NN 100000
#define EE 3200000
#define DD 64
#define NB_SCAN ((NN + 255) / 256)   // 391 blocks for scan

// ---------------- static device scratch (no runtime allocation) ----------------
static __device__ int     g_outcnt[NN];
static __device__ int     g_incnt[NN];
static __device__ float   g_outnorm[NN];
static __device__ float   g_innorm[NN];
static __device__ int     g_rowptr[NN + 1];
static __device__ int     g_cursor[NN];
static __device__ int     g_col[EE + NN];
static __device__ float2  g_p2[NN];          // (w*out_norm, out_norm) for rank-1 layer-1
static __device__ float2  g_ac[NN];          // scalar aggregation result (a, c)
static __device__ float   g_u[DD];           // W_in @ Wc0
static __device__ float   g_v[DD];           // b_in @ Wc0
static __device__ __half2 g_s16[NN * 32];    // fp16 scaled features (SpMM input)
static __device__ float   g_agg[NN * DD];    // fp32 aggregation output
static __device__ int     g_bsums[512];      // scan block sums

// ---------------- kernels ----------------

__global__ void k_zero() {
    int n = blockIdx.x * blockDim.x + threadIdx.x;
    if (n < NN) { g_outcnt[n] = 0; g_incnt[n] = 0; }
}

__global__ void k_degree(const int* __restrict__ src, const int* __restrict__ dst) {
    int e = blockIdx.x * blockDim.x + threadIdx.x;
    if (e < EE) {
        atomicAdd(&g_outcnt[src[e]], 1);
        atomicAdd(&g_incnt[dst[e]], 1);
    }
}

// norms + packed (w*on, on) for the rank-1 scalar SpMM
__global__ void k_norm(const float* __restrict__ weight) {
    int n = blockIdx.x * blockDim.x + threadIdx.x;
    if (n < NN) {
        float on = rsqrtf((float)(g_outcnt[n] + 1));   // +1 self loop => always >= 1
        float in = rsqrtf((float)(g_incnt[n] + 1));
        g_outnorm[n] = on;
        g_innorm[n]  = in;
        g_p2[n] = make_float2(weight[n] * on, on);
    }
}

// --- exclusive scan of deg[] = incnt[]+1 into rowptr ---
__global__ void k_scan1() {
    __shared__ int s[256];
    int t = threadIdx.x;
    int n = blockIdx.x * 256 + t;
    int v = (n < NN) ? (g_incnt[n] + 1) : 0;
    s[t] = v;
    __syncthreads();
    for (int off = 1; off < 256; off <<= 1) {
        int tmp = (t >= off) ? s[t - off] : 0;
        __syncthreads();
        s[t] += tmp;
        __syncthreads();
    }
    if (t == 255) g_bsums[blockIdx.x] = s[255];
}

__global__ void k_scan2() {
    __shared__ int s[512];
    int t = threadIdx.x;
    int v = (t < NB_SCAN) ? g_bsums[t] : 0;
    s[t] = v;
    __syncthreads();
    for (int off = 1; off < 512; off <<= 1) {
        int tmp = (t >= off) ? s[t - off] : 0;
        __syncthreads();
        s[t] += tmp;
        __syncthreads();
    }
    if (t < NB_SCAN) g_bsums[t] = s[t] - v;   // exclusive block offsets
}

__global__ void k_scan3() {
    __shared__ int s[256];
    int t = threadIdx.x;
    int n = blockIdx.x * 256 + t;
    int v = (n < NN) ? (g_incnt[n] + 1) : 0;
    s[t] = v;
    __syncthreads();
    for (int off = 1; off < 256; off <<= 1) {
        int tmp = (t >= off) ? s[t - off] : 0;
        __syncthreads();
        s[t] += tmp;
        __syncthreads();
    }
    if (n < NN) {
        int start = g_bsums[blockIdx.x] + s[t] - v;
        g_rowptr[n] = start;
        g_cursor[n] = start;
    }
    if (blockIdx.x == 0 && t == 0) g_rowptr[NN] = EE + NN;
}

__global__ void k_fill(const int* __restrict__ src, const int* __restrict__ dst) {
    int i = blockIdx.x * blockDim.x + threadIdx.x;
    if (i < EE + NN) {
        int s, d;
        if (i < EE) { s = src[i]; d = dst[i]; }
        else        { s = i - EE; d = s; }        // self loops
        int pos = atomicAdd(&g_cursor[d], 1);
        g_col[pos] = s;
    }
}

// scalar SpMM for rank-1 layer 1: (a, c) = sum over in-edges of (w*on, on)[src]
__global__ void k_spmm_scalar() {
    int gtid = blockIdx.x * blockDim.x + threadIdx.x;
    int n = gtid >> 5;
    int lane = gtid & 31;
    if (n >= NN) return;
    int beg = g_rowptr[n];
    int end = g_rowptr[n + 1];
    float ax = 0.f, cx = 0.f;
    for (int e = beg + lane; e < end; e += 32) {
        float2 p = g_p2[g_col[e]];
        ax += p.x;
        cx += p.y;
    }
    #pragma unroll
    for (int off = 16; off > 0; off >>= 1) {
        ax += __shfl_xor_sync(0xffffffffu, ax, off);
        cx += __shfl_xor_sync(0xffffffffu, cx, off);
    }
    if (lane == 0) g_ac[n] = make_float2(ax, cx);
}

// u = W_in @ Wc0, v = b_in @ Wc0  (tiny)
__global__ void k_uv(const float* __restrict__ Win,
                     const float* __restrict__ bin,
                     const float* __restrict__ Wc0) {
    int j = threadIdx.x;
    if (j < DD) {
        float u = 0.f, v = 0.f;
        #pragma unroll
        for (int k = 0; k < DD; k++) {
            float w = Wc0[k * DD + j];
            u += Win[k] * w;
            v += bin[k] * w;
        }
        g_u[j] = u;
        g_v[j] = v;
    }
}

// s1[n] = leaky( (a*in)*u + (c*in)*v + bc0 ) * on   -> fp16
__global__ void k_s1(const float* __restrict__ bc0) {
    int idx = blockIdx.x * blockDim.x + threadIdx.x;   // NN * 8 groups of 8 dims
    if (idx >= NN * 8) return;
    int n = idx >> 3;
    int j0 = (idx & 7) * 8;
    float2 ac = g_ac[n];
    float in = g_innorm[n];
    float on = g_outnorm[n];
    float alpha = ac.x * in;
    float gamma = ac.y * in;
    __half2 h[4];
    #pragma unroll
    for (int p = 0; p < 4; p++) {
        int j = j0 + p * 2;
        float y0 = alpha * g_u[j]     + gamma * g_v[j]     + bc0[j];
        float y1 = alpha * g_u[j + 1] + gamma * g_v[j + 1] + bc0[j + 1];
        y0 = (y0 > 0.f) ? y0 : 0.01f * y0;
        y1 = (y1 > 0.f) ? y1 : 0.01f * y1;
        h[p] = __floats2half2_rn(y0 * on, y1 * on);
    }
    *reinterpret_cast<uint4*>(&g_s16[n * 32 + (idx & 7) * 4]) =
        *reinterpret_cast<uint4*>(h);
}

// warp-per-node pull aggregation over fp16 features, fp32 accumulate
__global__ void k_spmm16() {
    int gtid = blockIdx.x * blockDim.x + threadIdx.x;
    int n = gtid >> 5;
    int lane = gtid & 31;
    if (n >= NN) return;
    int beg = g_rowptr[n];
    int end = g_rowptr[n + 1];
    float2 acc = make_float2(0.f, 0.f);
    for (int e = beg; e < end; e += 32) {
        int cnt = min(32, end - e);
        int idx = (lane < cnt) ? g_col[e + lane] : 0;
        #pragma unroll 8
        for (int j = 0; j < cnt; j++) {
            int srcn = __shfl_sync(0xffffffffu, idx, j);
            float2 v = __half22float2(g_s16[srcn * 32 + lane]);
            acc.x += v.x;
            acc.y += v.y;
        }
    }
    reinterpret_cast<float2*>(g_agg)[n * 32 + lane] = acc;
}

// fused dense: x = agg[n]*in_norm; y = x@W + b; then either
//   (non-final) s16[n] = leaky(y) * out_norm[n]   (fp16)
//   (final)     out[n] = y @ Wp + bp              (fp32)
__global__ void k_dense(const float* __restrict__ W,
                        const float* __restrict__ b,
                        int final_flag,
                        const float* __restrict__ Wp,
                        const float* __restrict__ bp,
                        float* __restrict__ out) {
    __shared__ float Ws[DD * DD];
    __shared__ float Bs[DD];
    __shared__ float Wps[DD];
    int t = threadIdx.x;
    {
        const float4* w4 = reinterpret_cast<const float4*>(W);
        float4* s4 = reinterpret_cast<float4*>(Ws);
        #pragma unroll
        for (int i = 0; i < 8; i++) s4[t + i * 128] = w4[t + i * 128];
        if (t < DD) { Bs[t] = b[t]; Wps[t] = Wp[t]; }
    }
    __syncthreads();

    int n = blockIdx.x * blockDim.x + t;
    if (n >= NN) return;

    float x[DD];
    {
        float sc = g_innorm[n];
        const float4* ap = reinterpret_cast<const float4*>(&g_agg[n * DD]);
        #pragma unroll
        for (int i = 0; i < 16; i++) {
            float4 v = ap[i];
            x[i * 4 + 0] = v.x * sc;
            x[i * 4 + 1] = v.y * sc;
            x[i * 4 + 2] = v.z * sc;
            x[i * 4 + 3] = v.w * sc;
        }
    }

    float on = g_outnorm[n];
    float pred = 0.f;
    #pragma unroll
    for (int c = 0; c < 4; c++) {
        float acc[16];
        #pragma unroll
        for (int o = 0; o < 16; o++) acc[o] = Bs[c * 16 + o];
        #pragma unroll
        for (int k = 0; k < DD; k++) {
            float xv = x[k];
            const float4* wr = reinterpret_cast<const float4*>(&Ws[k * DD + c * 16]);
            float4 w0 = wr[0], w1 = wr[1], w2 = wr[2], w3 = wr[3];
            acc[0]  += xv * w0.x;  acc[1]  += xv * w0.y;
            acc[2]  += xv * w0.z;  acc[3]  += xv * w0.w;
            acc[4]  += xv * w1.x;  acc[5]  += xv * w1.y;
            acc[6]  += xv * w1.z;  acc[7]  += xv * w1.w;
            acc[8]  += xv * w2.x;  acc[9]  += xv * w2.y;
            acc[10] += xv * w2.z;  acc[11] += xv * w2.w;
            acc[12] += xv * w3.x;  acc[13] += xv * w3.y;
            acc[14] += xv * w3.z;  acc[15] += xv * w3.w;
        }
        if (!final_flag) {
            __half2 h[8];
            #pragma unroll
            for (int o = 0; o < 8; o++) {
                float y0 = acc[o * 2];
                float y1 = acc[o * 2 + 1];
                y0 = (y0 > 0.f) ? y0 : 0.01f * y0;
                y1 = (y1 > 0.f) ? y1 : 0.01f * y1;
                h[o] = __floats2half2_rn(y0 * on, y1 * on);
            }
            uint4* op = reinterpret_cast<uint4*>(&g_s16[n * 32 + c * 8]);
            op[0] = *reinterpret_cast<uint4*>(&h[0]);
            op[1] = *reinterpret_cast<uint4*>(&h[4]);
        } else {
            #pragma unroll
            for (int o = 0; o < 16; o++) pred += acc[o] * Wps[c * 16 + o];
        }
    }
    if (final_flag) out[n] = pred + bp[0];
}

extern "C" void kernel_launch(void* const* d_in, const int* in_sizes, int n_in,
                              void* d_out, int out_size) {
    const float* weight = (const float*)d_in[0];
    const int*   src    = (const int*)d_in[1];
    const int*   dst    = (const int*)d_in[2];
    const float* W_in   = (const float*)d_in[3];
    const float* b_in   = (const float*)d_in[4];
    const float* Wc     = (const float*)d_in[5];   // [3,64,64]
    const float* bc     = (const float*)d_in[6];   // [3,64]
    const float* W_pred = (const float*)d_in[7];   // [64]
    const float* b_pred = (const float*)d_in[8];   // [1]
    float* out = (float*)d_out;

    const int TB = 256;
    // graph preprocessing
    k_zero<<<(NN + TB - 1) / TB, TB>>>();
    k_degree<<<(EE + TB - 1) / TB, TB>>>(src, dst);
    k_norm<<<(NN + TB - 1) / TB, TB>>>(weight);
    k_scan1<<<NB_SCAN, 256>>>();
    k_scan2<<<1, 512>>>();
    k_scan3<<<NB_SCAN, 256>>>();
    k_fill<<<(EE + NN + TB - 1) / TB, TB>>>(src, dst);

    // layer 1 via rank-1 factorization (scalar SpMM + closed-form dense)
    int spmm_blocks = (NN * 32 + TB - 1) / TB;
    k_spmm_scalar<<<spmm_blocks, TB>>>();
    k_uv<<<1, 64>>>(W_in, b_in, Wc);
    k_s1<<<(NN * 8 + TB - 1) / TB, TB>>>(bc);

    // layers 2, 3: fp16 SpMM + fp32 dense
    int dense_blocks = (NN + 127) / 128;
    for (int layer = 1; layer < 3; layer++) {
        k_spmm16<<<spmm_blocks, TB>>>();
        int fin = (layer == 2) ? 1 : 0;
        k_dense<<<dense_blocks, 128>>>(Wc + layer * DD * DD, bc + layer * DD,
                                       fin, W_pred, b_pred, out);
    }
}

// round 7
// speedup vs baseline: 1.3139x; 1.0126x over previous
#include <cuda_runtime.h>
#include <cuda_fp16.h>

// Problem constants (fixed shapes per reference)
#define NN 100000
#define EE 3200000
#define DD 64
#define NB_SCAN ((NN + 255) / 256)   // 391 blocks for scan

// ---------------- static device scratch (no runtime allocation) ----------------
static __device__ int     g_outcnt[NN];
static __device__ int     g_incnt[NN];
static __device__ float   g_outnorm[NN];
static __device__ float   g_innorm[NN];
static __device__ int     g_rowptr[NN + 1];
static __device__ int     g_cursor[NN];
static __device__ int     g_col[EE + NN];
static __device__ float2  g_p2[NN];          // (w*out_norm, out_norm) for rank-1 layer-1
static __device__ float2  g_ac[NN];          // scalar aggregation result (a, c)
static __device__ float   g_u[DD];           // W_in @ Wc0
static __device__ float   g_v[DD];           // b_in @ Wc0
static __device__ __half2 g_s16[NN * 32];    // fp16 scaled features, linear [n][64]
static __device__ float   g_agg[NN * DD];    // fp32 aggregation output
static __device__ int     g_bsums[512];      // scan block sums

// ---------------- graph preprocessing ----------------

__global__ void k_zero() {
    int n = blockIdx.x * blockDim.x + threadIdx.x;
    if (n < NN) { g_outcnt[n] = 0; g_incnt[n] = 0; }
}

__global__ void k_degree(const int* __restrict__ src, const int* __restrict__ dst) {
    int e = blockIdx.x * blockDim.x + threadIdx.x;
    if (e < EE) {
        atomicAdd(&g_outcnt[src[e]], 1);
        atomicAdd(&g_incnt[dst[e]], 1);
    }
}

__global__ void k_norm(const float* __restrict__ weight) {
    int n = blockIdx.x * blockDim.x + threadIdx.x;
    if (n < NN) {
        float on = rsqrtf((float)(g_outcnt[n] + 1));   // +1 self loop => always >= 1
        float in = rsqrtf((float)(g_incnt[n] + 1));
        g_outnorm[n] = on;
        g_innorm[n]  = in;
        g_p2[n] = make_float2(weight[n] * on, on);
    }
}

__global__ void k_scan1() {
    __shared__ int s[256];
    int t = threadIdx.x;
    int n = blockIdx.x * 256 + t;
    int v = (n < NN) ? (g_incnt[n] + 1) : 0;
    s[t] = v;
    __syncthreads();
    for (int off = 1; off < 256; off <<= 1) {
        int tmp = (t >= off) ? s[t - off] : 0;
        __syncthreads();
        s[t] += tmp;
        __syncthreads();
    }
    if (t == 255) g_bsums[blockIdx.x] = s[255];
}

__global__ void k_scan2() {
    __shared__ int s[512];
    int t = threadIdx.x;
    int v = (t < NB_SCAN) ? g_bsums[t] : 0;
    s[t] = v;
    __syncthreads();
    for (int off = 1; off < 512; off <<= 1) {
        int tmp = (t >= off) ? s[t - off] : 0;
        __syncthreads();
        s[t] += tmp;
        __syncthreads();
    }
    if (t < NB_SCAN) g_bsums[t] = s[t] - v;   // exclusive block offsets
}

__global__ void k_scan3() {
    __shared__ int s[256];
    int t = threadIdx.x;
    int n = blockIdx.x * 256 + t;
    int v = (n < NN) ? (g_incnt[n] + 1) : 0;
    s[t] = v;
    __syncthreads();
    for (int off = 1; off < 256; off <<= 1) {
        int tmp = (t >= off) ? s[t - off] : 0;
        __syncthreads();
        s[t] += tmp;
        __syncthreads();
    }
    if (n < NN) {
        int start = g_bsums[blockIdx.x] + s[t] - v;
        g_rowptr[n] = start;
        g_cursor[n] = start;
    }
    if (blockIdx.x == 0 && t == 0) g_rowptr[NN] = EE + NN;
}

__global__ void k_fill(const int* __restrict__ src, const int* __restrict__ dst) {
    int i = blockIdx.x * blockDim.x + threadIdx.x;
    if (i < EE + NN) {
        int s, d;
        if (i < EE) { s = src[i]; d = dst[i]; }
        else        { s = i - EE; d = s; }        // self loops
        int pos = atomicAdd(&g_cursor[d], 1);
        g_col[pos] = s;
    }
}

// ---------------- rank-1 first layer ----------------

__global__ void k_spmm_scalar() {
    int gtid = blockIdx.x * blockDim.x + threadIdx.x;
    int n = gtid >> 5;
    int lane = gtid & 31;
    if (n >= NN) return;
    int beg = g_rowptr[n];
    int end = g_rowptr[n + 1];
    float ax = 0.f, cx = 0.f;
    for (int e = beg + lane; e < end; e += 32) {
        float2 p = g_p2[g_col[e]];
        ax += p.x;
        cx += p.y;
    }
    #pragma unroll
    for (int off = 16; off > 0; off >>= 1) {
        ax += __shfl_xor_sync(0xffffffffu, ax, off);
        cx += __shfl_xor_sync(0xffffffffu, cx, off);
    }
    if (lane == 0) g_ac[n] = make_float2(ax, cx);
}

__global__ void k_uv(const float* __restrict__ Win,
                     const float* __restrict__ bin,
                     const float* __restrict__ Wc0) {
    int j = threadIdx.x;
    if (j < DD) {
        float u = 0.f, v = 0.f;
        #pragma unroll
        for (int k = 0; k < DD; k++) {
            float w = Wc0[k * DD + j];
            u += Win[k] * w;
            v += bin[k] * w;
        }
        g_u[j] = u;
        g_v[j] = v;
    }
}

// s1[n] = leaky( (a*in)*u + (c*in)*v + bc0 ) * on   -> fp16   (R2-exact, proven)
__global__ void k_s1(const float* __restrict__ bc0) {
    int idx = blockIdx.x * blockDim.x + threadIdx.x;   // NN * 8 groups of 8 dims
    if (idx >= NN * 8) return;
    int n = idx >> 3;
    int j0 = (idx & 7) * 8;
    float2 ac = g_ac[n];
    float in = g_innorm[n];
    float on = g_outnorm[n];
    float alpha = ac.x * in;
    float gamma = ac.y * in;
    __half2 h[4];
    #pragma unroll
    for (int p = 0; p < 4; p++) {
        int j = j0 + p * 2;
        float y0 = alpha * g_u[j]     + gamma * g_v[j]     + bc0[j];
        float y1 = alpha * g_u[j + 1] + gamma * g_v[j + 1] + bc0[j + 1];
        y0 = (y0 > 0.f) ? y0 : 0.01f * y0;
        y1 = (y1 > 0.f) ? y1 : 0.01f * y1;
        h[p] = __floats2half2_rn(y0 * on, y1 * on);
    }
    *reinterpret_cast<uint4*>(&g_s16[n * 32 + (idx & 7) * 4]) =
        *reinterpret_cast<uint4*>(h);
}

// ---------------- SpMM: 2 nodes per warp, 16 lanes each, 8B/lane gathers ----------------
// pure C++ (no local arrays, no inline asm); uint32 -> half2 via register bit ops.

__device__ __forceinline__ float2 u32_to_f2(unsigned u) {
    __half2 h = __halves2half2(__ushort_as_half((unsigned short)(u & 0xffffu)),
                               __ushort_as_half((unsigned short)(u >> 16)));
    return __half22float2(h);
}

__global__ void k_spmm16() {
    int gtid = blockIdx.x * blockDim.x + threadIdx.x;
    int n = gtid >> 4;      // node
    int s = gtid & 15;      // sublane: dims 4s..4s+3
    bool valid = (n < NN);
    int beg = valid ? g_rowptr[n] : 0;
    int end = valid ? g_rowptr[n + 1] : 0;
    int nb = (end - beg + 15) >> 4;
    int nbo = __shfl_xor_sync(0xffffffffu, nb, 16);
    int nbm = max(nb, nbo);                           // warp-uniform outer bound
    float a0 = 0.f, a1 = 0.f, a2 = 0.f, a3 = 0.f;
    const uint2* sp = reinterpret_cast<const uint2*>(g_s16);
    for (int it = 0; it < nbm; it++) {
        int e = beg + (it << 4);
        int cnt = min(16, end - e);                   // may be <= 0 for finished half
        int idx = (s < cnt) ? g_col[e + s] : 0;
        int cnto = __shfl_xor_sync(0xffffffffu, cnt, 16);
        int cntm = max(cnt, cnto);                    // warp-uniform inner bound
        for (int j = 0; j < cntm; j++) {
            int srcn = __shfl_sync(0xffffffffu, idx, j, 16);
            if (j < cnt) {
                uint2 v = sp[srcn * 16 + s];
                float2 f0 = u32_to_f2(v.x);
                float2 f1 = u32_to_f2(v.y);
                a0 += f0.x; a1 += f0.y;
                a2 += f1.x; a3 += f1.y;
            }
        }
    }
    if (valid)
        reinterpret_cast<float4*>(g_agg)[n * 16 + s] = make_float4(a0, a1, a2, a3);
}

// ---------------- dense (R2-exact FFMA, proven zero-local) ----------------
// x = agg[n]*in_norm; y = x@W + b; then either
//   (non-final) s16[n] = leaky(y) * out_norm[n]   (fp16)
//   (final)     out[n] = y @ Wp + bp              (fp32)

__global__ void k_dense(const float* __restrict__ W,
                        const float* __restrict__ b,
                        int final_flag,
                        const float* __restrict__ Wp,
                        const float* __restrict__ bp,
                        float* __restrict__ out) {
    __shared__ float Ws[DD * DD];
    __shared__ float Bs[DD];
    __shared__ float Wps[DD];
    int t = threadIdx.x;
    {
        const float4* w4 = reinterpret_cast<const float4*>(W);
        float4* s4 = reinterpret_cast<float4*>(Ws);
        #pragma unroll
        for (int i = 0; i < 8; i++) s4[t + i * 128] = w4[t + i * 128];
        if (t < DD) { Bs[t] = b[t]; Wps[t] = Wp[t]; }
    }
    __syncthreads();

    int n = blockIdx.x * blockDim.x + t;
    if (n >= NN) return;

    float x[DD];
    {
        float sc = g_innorm[n];
        const float4* ap = reinterpret_cast<const float4*>(&g_agg[n * DD]);
        #pragma unroll
        for (int i = 0; i < 16; i++) {
            float4 v = ap[i];
            x[i * 4 + 0] = v.x * sc;
            x[i * 4 + 1] = v.y * sc;
            x[i * 4 + 2] = v.z * sc;
            x[i * 4 + 3] = v.w * sc;
        }
    }

    float on = g_outnorm[n];
    float pred = 0.f;
    #pragma unroll
    for (int c = 0; c < 4; c++) {
        float acc[16];
        #pragma unroll
        for (int o = 0; o < 16; o++) acc[o] = Bs[c * 16 + o];
        #pragma unroll
        for (int k = 0; k < DD; k++) {
            float xv = x[k];
            const float4* wr = reinterpret_cast<const float4*>(&Ws[k * DD + c * 16]);
            float4 w0 = wr[0], w1 = wr[1], w2 = wr[2], w3 = wr[3];
            acc[0]  += xv * w0.x;  acc[1]  += xv * w0.y;
            acc[2]  += xv * w0.z;  acc[3]  += xv * w0.w;
            acc[4]  += xv * w1.x;  acc[5]  += xv * w1.y;
            acc[6]  += xv * w1.z;  acc[7]  += xv * w1.w;
            acc[8]  += xv * w2.x;  acc[9]  += xv * w2.y;
            acc[10] += xv * w2.z;  acc[11] += xv * w2.w;
            acc[12] += xv * w3.x;  acc[13] += xv * w3.y;
            acc[14] += xv * w3.z;  acc[15] += xv * w3.w;
        }
        if (!final_flag) {
            __half2 h[8];
            #pragma unroll
            for (int o = 0; o < 8; o++) {
                float y0 = acc[o * 2];
                float y1 = acc[o * 2 + 1];
                y0 = (y0 > 0.f) ? y0 : 0.01f * y0;
                y1 = (y1 > 0.f) ? y1 : 0.01f * y1;
                h[o] = __floats2half2_rn(y0 * on, y1 * on);
            }
            uint4* op = reinterpret_cast<uint4*>(&g_s16[n * 32 + c * 8]);
            op[0] = *reinterpret_cast<uint4*>(&h[0]);
            op[1] = *reinterpret_cast<uint4*>(&h[4]);
        } else {
            #pragma unroll
            for (int o = 0; o < 16; o++) pred += acc[o] * Wps[c * 16 + o];
        }
    }
    if (final_flag) out[n] = pred + bp[0];
}

// ---------------- launch ----------------

extern "C" void kernel_launch(void* const* d_in, const int* in_sizes, int n_in,
                              void* d_out, int out_size) {
    const float* weight = (const float*)d_in[0];
    const int*   src    = (const int*)d_in[1];
    const int*   dst    = (const int*)d_in[2];
    const float* W_in   = (const float*)d_in[3];
    const float* b_in   = (const float*)d_in[4];
    const float* Wc     = (const float*)d_in[5];   // [3,64,64]
    const float* bc     = (const float*)d_in[6];   // [3,64]
    const float* W_pred = (const float*)d_in[7];   // [64]
    const float* b_pred = (const float*)d_in[8];   // [1]
    float* out = (float*)d_out;

    const int TB = 256;
    // graph preprocessing
    k_zero<<<(NN + TB - 1) / TB, TB>>>();
    k_degree<<<(EE + TB - 1) / TB, TB>>>(src, dst);
    k_norm<<<(NN + TB - 1) / TB, TB>>>(weight);
    k_scan1<<<NB_SCAN, 256>>>();
    k_scan2<<<1, 512>>>();
    k_scan3<<<NB_SCAN, 256>>>();
    k_fill<<<(EE + NN + TB - 1) / TB, TB>>>(src, dst);

    // layer 1 via rank-1 factorization (scalar SpMM + closed-form dense)
    k_spmm_scalar<<<(NN * 32 + TB - 1) / TB, TB>>>();
    k_uv<<<1, 64>>>(W_in, b_in, Wc);
    k_s1<<<(NN * 8 + TB - 1) / TB, TB>>>(bc);

    // layers 2, 3: fp16 SpMM + fp32 dense
    int spmm_blocks = (NN * 16 + TB - 1) / TB;
    int dense_blocks = (NN + 127) / 128;
    for (int layer = 1; layer < 3; layer++) {
        k_spmm16<<<spmm_blocks, TB>>>();
        int fin = (layer == 2) ? 1 : 0;
        k_dense<<<dense_blocks, 128>>>(Wc + layer * DD * DD, bc + layer * DD,
                                       fin, W_pred, b_pred, out);
    }
}

// round 9
// speedup vs baseline: 1.6749x; 1.2747x over previous
#include <cuda_runtime.h>
#include <cuda_fp16.h>

// Problem constants (fixed shapes per reference)
#define NN 100000
#define EE 3200000
#define DD 64
#define NB_SCAN ((NN + 255) / 256)   // 391 blocks for scan

// ---------------- static device scratch (no runtime allocation) ----------------
static __device__ int     g_outcnt[NN];
static __device__ int     g_incnt[NN];
static __device__ float   g_outnorm[NN];
static __device__ float   g_innorm[NN];
static __device__ int     g_rowptr[NN + 1];
static __device__ int     g_cursor[NN];
static __device__ int     g_col[EE + NN];
static __device__ float2  g_p2[NN];          // (w*out_norm, out_norm) for rank-1 layer-1
static __device__ float2  g_ac[NN];          // scalar aggregation result (a, c)
static __device__ float   g_u[DD];           // W_in @ Wc0
static __device__ float   g_v[DD];           // b_in @ Wc0
static __device__ float   g_wt[DD];          // Wc2 @ Wp  (layer-3 collapse vector)
static __device__ float   g_c0[1];           // bc2 . Wp + bp
static __device__ __half2 g_s16[NN * 32];    // fp16 scaled features s1, linear [n][64]
static __device__ float   g_agg[NN * DD];    // fp32 aggregation output (layer 2)
static __device__ float   g_z[NN];           // scalar z = s2 . wt
static __device__ int     g_bsums[512];      // scan block sums

// ---------------- graph preprocessing ----------------

__global__ void k_zero() {
    int n = blockIdx.x * blockDim.x + threadIdx.x;
    if (n < NN) { g_outcnt[n] = 0; g_incnt[n] = 0; }
}

__global__ void k_degree(const int* __restrict__ src, const int* __restrict__ dst) {
    int e = blockIdx.x * blockDim.x + threadIdx.x;
    if (e < EE) {
        atomicAdd(&g_outcnt[src[e]], 1);
        atomicAdd(&g_incnt[dst[e]], 1);
    }
}

__global__ void k_norm(const float* __restrict__ weight) {
    int n = blockIdx.x * blockDim.x + threadIdx.x;
    if (n < NN) {
        float on = rsqrtf((float)(g_outcnt[n] + 1));   // +1 self loop => always >= 1
        float in = rsqrtf((float)(g_incnt[n] + 1));
        g_outnorm[n] = on;
        g_innorm[n]  = in;
        g_p2[n] = make_float2(weight[n] * on, on);
    }
}

__global__ void k_scan1() {
    __shared__ int s[256];
    int t = threadIdx.x;
    int n = blockIdx.x * 256 + t;
    int v = (n < NN) ? (g_incnt[n] + 1) : 0;
    s[t] = v;
    __syncthreads();
    for (int off = 1; off < 256; off <<= 1) {
        int tmp = (t >= off) ? s[t - off] : 0;
        __syncthreads();
        s[t] += tmp;
        __syncthreads();
    }
    if (t == 255) g_bsums[blockIdx.x] = s[255];
}

__global__ void k_scan2() {
    __shared__ int s[512];
    int t = threadIdx.x;
    int v = (t < NB_SCAN) ? g_bsums[t] : 0;
    s[t] = v;
    __syncthreads();
    for (int off = 1; off < 512; off <<= 1) {
        int tmp = (t >= off) ? s[t - off] : 0;
        __syncthreads();
        s[t] += tmp;
        __syncthreads();
    }
    if (t < NB_SCAN) g_bsums[t] = s[t] - v;   // exclusive block offsets
}

__global__ void k_scan3() {
    __shared__ int s[256];
    int t = threadIdx.x;
    int n = blockIdx.x * 256 + t;
    int v = (n < NN) ? (g_incnt[n] + 1) : 0;
    s[t] = v;
    __syncthreads();
    for (int off = 1; off < 256; off <<= 1) {
        int tmp = (t >= off) ? s[t - off] : 0;
        __syncthreads();
        s[t] += tmp;
        __syncthreads();
    }
    if (n < NN) {
        int start = g_bsums[blockIdx.x] + s[t] - v;
        g_rowptr[n] = start;
        g_cursor[n] = start;
    }
    if (blockIdx.x == 0 && t == 0) g_rowptr[NN] = EE + NN;
}

__global__ void k_fill(const int* __restrict__ src, const int* __restrict__ dst) {
    int i = blockIdx.x * blockDim.x + threadIdx.x;
    if (i < EE + NN) {
        int s, d;
        if (i < EE) { s = src[i]; d = dst[i]; }
        else        { s = i - EE; d = s; }        // self loops
        int pos = atomicAdd(&g_cursor[d], 1);
        g_col[pos] = s;
    }
}

// ---------------- tiny parameter transforms ----------------

// u = W_in @ Wc0, v = b_in @ Wc0
__global__ void k_uv(const float* __restrict__ Win,
                     const float* __restrict__ bin,
                     const float* __restrict__ Wc0) {
    int j = threadIdx.x;
    if (j < DD) {
        float u = 0.f, v = 0.f;
        #pragma unroll
        for (int k = 0; k < DD; k++) {
            float w = Wc0[k * DD + j];
            u += Win[k] * w;
            v += bin[k] * w;
        }
        g_u[j] = u;
        g_v[j] = v;
    }
}

// wt = Wc2 @ Wp (64-vec); c0 = bc2 . Wp + bp
__global__ void k_wt(const float* __restrict__ Wc,
                     const float* __restrict__ bc,
                     const float* __restrict__ Wp,
                     const float* __restrict__ bp) {
    int t = threadIdx.x;
    if (t < DD) {
        float s = 0.f;
        #pragma unroll
        for (int n = 0; n < DD; n++)
            s += Wc[2 * DD * DD + t * DD + n] * Wp[n];
        g_wt[t] = s;
    } else if (t == DD) {
        float s = 0.f;
        for (int n = 0; n < DD; n++)
            s += bc[2 * DD + n] * Wp[n];
        g_c0[0] = s + bp[0];
    }
}

// ---------------- rank-1 first layer ----------------

__global__ void k_spmm_scalar() {
    int gtid = blockIdx.x * blockDim.x + threadIdx.x;
    int n = gtid >> 5;
    int lane = gtid & 31;
    if (n >= NN) return;
    int beg = g_rowptr[n];
    int end = g_rowptr[n + 1];
    float ax = 0.f, cx = 0.f;
    for (int e = beg + lane; e < end; e += 32) {
        float2 p = g_p2[g_col[e]];
        ax += p.x;
        cx += p.y;
    }
    #pragma unroll
    for (int off = 16; off > 0; off >>= 1) {
        ax += __shfl_xor_sync(0xffffffffu, ax, off);
        cx += __shfl_xor_sync(0xffffffffu, cx, off);
    }
    if (lane == 0) g_ac[n] = make_float2(ax, cx);
}

// s1[n] = leaky( (a*in)*u + (c*in)*v + bc0 ) * on   -> fp16   (R2-exact, proven)
__global__ void k_s1(const float* __restrict__ bc0) {
    int idx = blockIdx.x * blockDim.x + threadIdx.x;   // NN * 8 groups of 8 dims
    if (idx >= NN * 8) return;
    int n = idx >> 3;
    int j0 = (idx & 7) * 8;
    float2 ac = g_ac[n];
    float in = g_innorm[n];
    float on = g_outnorm[n];
    float alpha = ac.x * in;
    float gamma = ac.y * in;
    __half2 h[4];
    #pragma unroll
    for (int p = 0; p < 4; p++) {
        int j = j0 + p * 2;
        float y0 = alpha * g_u[j]     + gamma * g_v[j]     + bc0[j];
        float y1 = alpha * g_u[j + 1] + gamma * g_v[j + 1] + bc0[j + 1];
        y0 = (y0 > 0.f) ? y0 : 0.01f * y0;
        y1 = (y1 > 0.f) ? y1 : 0.01f * y1;
        h[p] = __floats2half2_rn(y0 * on, y1 * on);
    }
    *reinterpret_cast<uint4*>(&g_s16[n * 32 + (idx & 7) * 4]) =
        *reinterpret_cast<uint4*>(h);
}

// ---------------- SpMM: 2 nodes per warp, 16 lanes each, 8B/lane gathers ----------------

__device__ __forceinline__ float2 u32_to_f2(unsigned u) {
    __half2 h = __halves2half2(__ushort_as_half((unsigned short)(u & 0xffffu)),
                               __ushort_as_half((unsigned short)(u >> 16)));
    return __half22float2(h);
}

__global__ void k_spmm16() {
    int gtid = blockIdx.x * blockDim.x + threadIdx.x;
    int n = gtid >> 4;      // node
    int s = gtid & 15;      // sublane: dims 4s..4s+3
    bool valid = (n < NN);
    int beg = valid ? g_rowptr[n] : 0;
    int end = valid ? g_rowptr[n + 1] : 0;
    int nb = (end - beg + 15) >> 4;
    int nbo = __shfl_xor_sync(0xffffffffu, nb, 16);
    int nbm = max(nb, nbo);                           // warp-uniform outer bound
    float a0 = 0.f, a1 = 0.f, a2 = 0.f, a3 = 0.f;
    const uint2* sp = reinterpret_cast<const uint2*>(g_s16);
    for (int it = 0; it < nbm; it++) {
        int e = beg + (it << 4);
        int cnt = min(16, end - e);                   // may be <= 0 for finished half
        int idx = (s < cnt) ? g_col[e + s] : 0;
        int cnto = __shfl_xor_sync(0xffffffffu, cnt, 16);
        int cntm = max(cnt, cnto);                    // warp-uniform inner bound
        for (int j = 0; j < cntm; j++) {
            int srcn = __shfl_sync(0xffffffffu, idx, j, 16);
            if (j < cnt) {
                uint2 v = sp[srcn * 16 + s];
                float2 f0 = u32_to_f2(v.x);
                float2 f1 = u32_to_f2(v.y);
                a0 += f0.x; a1 += f0.y;
                a2 += f1.x; a3 += f1.y;
            }
        }
    }
    if (valid)
        reinterpret_cast<float4*>(g_agg)[n * 16 + s] = make_float4(a0, a1, a2, a3);
}

// ---------------- dense layer 2 + layer-3 collapse (R2-proven FFMA pattern) ----------------
// x = agg[n]*in; y = x@Wc1 + bc1; z[n] = on * sum_o leaky(y_o) * wt_o

__global__ void k_dense_z(const float* __restrict__ W,
                          const float* __restrict__ b) {
    __shared__ float Ws[DD * DD];
    __shared__ float Bs[DD];
    __shared__ float Wts[DD];
    int t = threadIdx.x;
    {
        const float4* w4 = reinterpret_cast<const float4*>(W);
        float4* s4 = reinterpret_cast<float4*>(Ws);
        #pragma unroll
        for (int i = 0; i < 8; i++) s4[t + i * 128] = w4[t + i * 128];
        if (t < DD) { Bs[t] = b[t]; Wts[t] = g_wt[t]; }
    }
    __syncthreads();

    int n = blockIdx.x * blockDim.x + t;
    if (n >= NN) return;

    float x[DD];
    {
        float sc = g_innorm[n];
        const float4* ap = reinterpret_cast<const float4*>(&g_agg[n * DD]);
        #pragma unroll
        for (int i = 0; i < 16; i++) {
            float4 v = ap[i];
            x[i * 4 + 0] = v.x * sc;
            x[i * 4 + 1] = v.y * sc;
            x[i * 4 + 2] = v.z * sc;
            x[i * 4 + 3] = v.w * sc;
        }
    }

    float z = 0.f;
    #pragma unroll
    for (int c = 0; c < 4; c++) {
        float acc[16];
        #pragma unroll
        for (int o = 0; o < 16; o++) acc[o] = Bs[c * 16 + o];
        #pragma unroll
        for (int k = 0; k < DD; k++) {
            float xv = x[k];
            const float4* wr = reinterpret_cast<const float4*>(&Ws[k * DD + c * 16]);
            float4 w0 = wr[0], w1 = wr[1], w2 = wr[2], w3 = wr[3];
            acc[0]  += xv * w0.x;  acc[1]  += xv * w0.y;
            acc[2]  += xv * w0.z;  acc[3]  += xv * w0.w;
            acc[4]  += xv * w1.x;  acc[5]  += xv * w1.y;
            acc[6]  += xv * w1.z;  acc[7]  += xv * w1.w;
            acc[8]  += xv * w2.x;  acc[9]  += xv * w2.y;
            acc[10] += xv * w2.z;  acc[11] += xv * w2.w;
            acc[12] += xv * w3.x;  acc[13] += xv * w3.y;
            acc[14] += xv * w3.z;  acc[15] += xv * w3.w;
        }
        #pragma unroll
        for (int o = 0; o < 16; o++) {
            float y = acc[o];
            y = (y > 0.f) ? y : 0.01f * y;
            z += y * Wts[c * 16 + o];
        }
    }
    g_z[n] = z * g_outnorm[n];
}

// ---------------- layer-3 scalar segment-sum + output ----------------
// out[n] = in[n] * sum over in-edges of z[src] + c0

__global__ void k_spmm_z(float* __restrict__ out) {
    int gtid = blockIdx.x * blockDim.x + threadIdx.x;
    int n = gtid >> 5;
    int lane = gtid & 31;
    if (n >= NN) return;
    int beg = g_rowptr[n];
    int end = g_rowptr[n + 1];
    float s = 0.f;
    for (int e = beg + lane; e < end; e += 32) {
        s += g_z[g_col[e]];
    }
    #pragma unroll
    for (int off = 16; off > 0; off >>= 1)
        s += __shfl_xor_sync(0xffffffffu, s, off);
    if (lane == 0) out[n] = g_innorm[n] * s + g_c0[0];
}

// ---------------- launch ----------------

extern "C" void kernel_launch(void* const* d_in, const int* in_sizes, int n_in,
                              void* d_out, int out_size) {
    const float* weight = (const float*)d_in[0];
    const int*   src    = (const int*)d_in[1];
    const int*   dst    = (const int*)d_in[2];
    const float* W_in   = (const float*)d_in[3];
    const float* b_in   = (const float*)d_in[4];
    const float* Wc     = (const float*)d_in[5];   // [3,64,64]
    const float* bc     = (const float*)d_in[6];   // [3,64]
    const float* W_pred = (const float*)d_in[7];   // [64]
    const float* b_pred = (const float*)d_in[8];   // [1]
    float* out = (float*)d_out;

    const int TB = 256;
    // graph preprocessing
    k_zero<<<(NN + TB - 1) / TB, TB>>>();
    k_degree<<<(EE + TB - 1) / TB, TB>>>(src, dst);
    k_norm<<<(NN + TB - 1) / TB, TB>>>(weight);
    k_scan1<<<NB_SCAN, 256>>>();
    k_scan2<<<1, 512>>>();
    k_scan3<<<NB_SCAN, 256>>>();
    k_fill<<<(EE + NN + TB - 1) / TB, TB>>>(src, dst);

    // tiny parameter transforms
    k_uv<<<1, 64>>>(W_in, b_in, Wc);
    k_wt<<<1, 128>>>(Wc, bc, W_pred, b_pred);

    // layer 1 via rank-1 factorization (scalar SpMM + closed-form features)
    k_spmm_scalar<<<(NN * 32 + TB - 1) / TB, TB>>>();
    k_s1<<<(NN * 8 + TB - 1) / TB, TB>>>(bc);

    // layer 2: the single vector SpMM + dense (with layer-3 collapse into z)
    k_spmm16<<<(NN * 16 + TB - 1) / TB, TB>>>();
    k_dense_z<<<(NN + 127) / 128, 128>>>(Wc + DD * DD, bc + DD);

    // layer 3: scalar segment-sum of z + output
    k_spmm_z<<<(NN * 32 + TB - 1) / TB, TB>>>(out);
}

// round 10
// speedup vs baseline: 1.6823x; 1.0044x over previous
#include <cuda_runtime.h>
#include <cuda_fp16.h>

// Problem constants (fixed shapes per reference)
#define NN 100000
#define EE 3200000
#define DD 64
#define NB_SCAN ((NN + 255) / 256)   // 391 blocks for scan

// ---------------- static device scratch (no runtime allocation) ----------------
static __device__ int     g_outcnt[NN];
static __device__ int     g_incnt[NN];
static __device__ float   g_outnorm[NN];
static __device__ float   g_innorm[NN];
static __device__ int     g_rowptr[NN + 1];
static __device__ int     g_cursor[NN];
static __device__ int     g_col[EE + NN];
static __device__ float2  g_p2[NN];          // (w*out_norm, out_norm) for rank-1 layer-1
static __device__ float   g_a[NN];           // push-aggregated sum of w*on over in-nbrs
static __device__ float   g_c[NN];           // push-aggregated sum of on over in-nbrs
static __device__ float   g_u[DD];           // W_in @ Wc0
static __device__ float   g_v[DD];           // b_in @ Wc0
static __device__ float   g_wt[DD];          // Wc2 @ Wp  (layer-3 collapse vector)
static __device__ float   g_c0[1];           // bc2 . Wp + bp
static __device__ __half2 g_s16[NN * 32];    // fp16 scaled features s1, linear [n][64]
static __device__ float   g_agg[NN * DD];    // fp32 aggregation output (layer 2)
static __device__ float   g_z[NN];           // scalar z = s2 . wt
static __device__ int     g_bsums[512];      // scan block sums

// ---------------- graph preprocessing ----------------

__global__ void k_zero() {
    int n = blockIdx.x * blockDim.x + threadIdx.x;
    if (n < NN) {
        g_outcnt[n] = 0; g_incnt[n] = 0;
        g_a[n] = 0.f;    g_c[n] = 0.f;
    }
}

__global__ void k_degree(const int* __restrict__ src, const int* __restrict__ dst) {
    int e = blockIdx.x * blockDim.x + threadIdx.x;
    if (e < EE) {
        atomicAdd(&g_outcnt[src[e]], 1);
        atomicAdd(&g_incnt[dst[e]], 1);
    }
}

__global__ void k_norm(const float* __restrict__ weight) {
    int n = blockIdx.x * blockDim.x + threadIdx.x;
    if (n < NN) {
        float on = rsqrtf((float)(g_outcnt[n] + 1));   // +1 self loop => always >= 1
        float in = rsqrtf((float)(g_incnt[n] + 1));
        g_outnorm[n] = on;
        g_innorm[n]  = in;
        g_p2[n] = make_float2(weight[n] * on, on);
    }
}

__global__ void k_scan1() {
    __shared__ int s[256];
    int t = threadIdx.x;
    int n = blockIdx.x * 256 + t;
    int v = (n < NN) ? (g_incnt[n] + 1) : 0;
    s[t] = v;
    __syncthreads();
    for (int off = 1; off < 256; off <<= 1) {
        int tmp = (t >= off) ? s[t - off] : 0;
        __syncthreads();
        s[t] += tmp;
        __syncthreads();
    }
    if (t == 255) g_bsums[blockIdx.x] = s[255];
}

__global__ void k_scan2() {
    __shared__ int s[512];
    int t = threadIdx.x;
    int v = (t < NB_SCAN) ? g_bsums[t] : 0;
    s[t] = v;
    __syncthreads();
    for (int off = 1; off < 512; off <<= 1) {
        int tmp = (t >= off) ? s[t - off] : 0;
        __syncthreads();
        s[t] += tmp;
        __syncthreads();
    }
    if (t < NB_SCAN) g_bsums[t] = s[t] - v;   // exclusive block offsets
}

__global__ void k_scan3() {
    __shared__ int s[256];
    int t = threadIdx.x;
    int n = blockIdx.x * 256 + t;
    int v = (n < NN) ? (g_incnt[n] + 1) : 0;
    s[t] = v;
    __syncthreads();
    for (int off = 1; off < 256; off <<= 1) {
        int tmp = (t >= off) ? s[t - off] : 0;
        __syncthreads();
        s[t] += tmp;
        __syncthreads();
    }
    if (n < NN) {
        int start = g_bsums[blockIdx.x] + s[t] - v;
        g_rowptr[n] = start;
        g_cursor[n] = start;
    }
    if (blockIdx.x == 0 && t == 0) g_rowptr[NN] = EE + NN;
}

// CSR fill + fused push-aggregation of the rank-1 layer-1 scalars
__global__ void k_fill(const int* __restrict__ src, const int* __restrict__ dst) {
    int i = blockIdx.x * blockDim.x + threadIdx.x;
    if (i < EE + NN) {
        int s, d;
        if (i < EE) { s = src[i]; d = dst[i]; }
        else        { s = i - EE; d = s; }        // self loops
        int pos = atomicAdd(&g_cursor[d], 1);
        g_col[pos] = s;
        float2 p = g_p2[s];
        atomicAdd(&g_a[d], p.x);
        atomicAdd(&g_c[d], p.y);
    }
}

// ---------------- tiny parameter transforms (merged) ----------------
// t<64: u,v = (W_in, b_in) @ Wc0 ; t in [64,128): wt = Wc2 @ Wp ; t==128: c0

__global__ void k_uvwt(const float* __restrict__ Win,
                       const float* __restrict__ bin,
                       const float* __restrict__ Wc,
                       const float* __restrict__ bc,
                       const float* __restrict__ Wp,
                       const float* __restrict__ bp) {
    int t = threadIdx.x;
    if (t < DD) {
        float u = 0.f, v = 0.f;
        #pragma unroll
        for (int k = 0; k < DD; k++) {
            float w = Wc[k * DD + t];
            u += Win[k] * w;
            v += bin[k] * w;
        }
        g_u[t] = u;
        g_v[t] = v;
    } else if (t < 2 * DD) {
        int j = t - DD;
        float s = 0.f;
        #pragma unroll
        for (int n = 0; n < DD; n++)
            s += Wc[2 * DD * DD + j * DD + n] * Wp[n];
        g_wt[j] = s;
    } else if (t == 2 * DD) {
        float s = 0.f;
        for (int n = 0; n < DD; n++)
            s += bc[2 * DD + n] * Wp[n];
        g_c0[0] = s + bp[0];
    }
}

// s1[n] = leaky( (a*in)*u + (c*in)*v + bc0 ) * on   -> fp16
__global__ void k_s1(const float* __restrict__ bc0) {
    int idx = blockIdx.x * blockDim.x + threadIdx.x;   // NN * 8 groups of 8 dims
    if (idx >= NN * 8) return;
    int n = idx >> 3;
    int j0 = (idx & 7) * 8;
    float in = g_innorm[n];
    float on = g_outnorm[n];
    float alpha = g_a[n] * in;
    float gamma = g_c[n] * in;
    __half2 h[4];
    #pragma unroll
    for (int p = 0; p < 4; p++) {
        int j = j0 + p * 2;
        float y0 = alpha * g_u[j]     + gamma * g_v[j]     + bc0[j];
        float y1 = alpha * g_u[j + 1] + gamma * g_v[j + 1] + bc0[j + 1];
        y0 = (y0 > 0.f) ? y0 : 0.01f * y0;
        y1 = (y1 > 0.f) ? y1 : 0.01f * y1;
        h[p] = __floats2half2_rn(y0 * on, y1 * on);
    }
    *reinterpret_cast<uint4*>(&g_s16[n * 32 + (idx & 7) * 4]) =
        *reinterpret_cast<uint4*>(h);
}

// ---------------- SpMM: 2 nodes per warp, 16 lanes each, 8B/lane gathers ----------------
// fast path: when both half-warps have a full block of 16 edges, fully unrolled
// inner loop -> 16 outstanding gathers (MLP).

__device__ __forceinline__ float2 u32_to_f2(unsigned u) {
    __half2 h = __halves2half2(__ushort_as_half((unsigned short)(u & 0xffffu)),
                               __ushort_as_half((unsigned short)(u >> 16)));
    return __half22float2(h);
}

__global__ void k_spmm16() {
    int gtid = blockIdx.x * blockDim.x + threadIdx.x;
    int n = gtid >> 4;      // node
    int s = gtid & 15;      // sublane: dims 4s..4s+3
    bool valid = (n < NN);
    int beg = valid ? g_rowptr[n] : 0;
    int end = valid ? g_rowptr[n + 1] : 0;
    int nb = (end - beg + 15) >> 4;
    int nbo = __shfl_xor_sync(0xffffffffu, nb, 16);
    int nbm = max(nb, nbo);                           // warp-uniform outer bound
    float a0 = 0.f, a1 = 0.f, a2 = 0.f, a3 = 0.f;
    const uint2* sp = reinterpret_cast<const uint2*>(g_s16);
    for (int it = 0; it < nbm; it++) {
        int e = beg + (it << 4);
        int cnt = min(16, end - e);                   // may be <= 0 for finished half
        int idx = (s < cnt) ? g_col[e + s] : 0;
        int cnto = __shfl_xor_sync(0xffffffffu, cnt, 16);
        if (min(cnt, cnto) == 16) {
            // both halves full: unrolled, independent gathers
            #pragma unroll
            for (int j = 0; j < 16; j++) {
                int srcn = __shfl_sync(0xffffffffu, idx, j, 16);
                uint2 v = sp[srcn * 16 + s];
                float2 f0 = u32_to_f2(v.x);
                float2 f1 = u32_to_f2(v.y);
                a0 += f0.x; a1 += f0.y;
                a2 += f1.x; a3 += f1.y;
            }
        } else {
            int cntm = max(cnt, cnto);                // warp-uniform inner bound
            for (int j = 0; j < cntm; j++) {
                int srcn = __shfl_sync(0xffffffffu, idx, j, 16);
                if (j < cnt) {
                    uint2 v = sp[srcn * 16 + s];
                    float2 f0 = u32_to_f2(v.x);
                    float2 f1 = u32_to_f2(v.y);
                    a0 += f0.x; a1 += f0.y;
                    a2 += f1.x; a3 += f1.y;
                }
            }
        }
    }
    if (valid)
        reinterpret_cast<float4*>(g_agg)[n * 16 + s] = make_float4(a0, a1, a2, a3);
}

// ---------------- dense layer 2 + layer-3 collapse (proven FFMA pattern) ----------------
// x = agg[n]*in; y = x@Wc1 + bc1; z[n] = on * sum_o leaky(y_o) * wt_o

__global__ void k_dense_z(const float* __restrict__ W,
                          const float* __restrict__ b) {
    __shared__ float Ws[DD * DD];
    __shared__ float Bs[DD];
    __shared__ float Wts[DD];
    int t = threadIdx.x;
    {
        const float4* w4 = reinterpret_cast<const float4*>(W);
        float4* s4 = reinterpret_cast<float4*>(Ws);
        #pragma unroll
        for (int i = 0; i < 8; i++) s4[t + i * 128] = w4[t + i * 128];
        if (t < DD) { Bs[t] = b[t]; Wts[t] = g_wt[t]; }
    }
    __syncthreads();

    int n = blockIdx.x * blockDim.x + t;
    if (n >= NN) return;

    float x[DD];
    {
        float sc = g_innorm[n];
        const float4* ap = reinterpret_cast<const float4*>(&g_agg[n * DD]);
        #pragma unroll
        for (int i = 0; i < 16; i++) {
            float4 v = ap[i];
            x[i * 4 + 0] = v.x * sc;
            x[i * 4 + 1] = v.y * sc;
            x[i * 4 + 2] = v.z * sc;
            x[i * 4 + 3] = v.w * sc;
        }
    }

    float z = 0.f;
    #pragma unroll
    for (int c = 0; c < 4; c++) {
        float acc[16];
        #pragma unroll
        for (int o = 0; o < 16; o++) acc[o] = Bs[c * 16 + o];
        #pragma unroll
        for (int k = 0; k < DD; k++) {
            float xv = x[k];
            const float4* wr = reinterpret_cast<const float4*>(&Ws[k * DD + c * 16]);
            float4 w0 = wr[0], w1 = wr[1], w2 = wr[2], w3 = wr[3];
            acc[0]  += xv * w0.x;  acc[1]  += xv * w0.y;
            acc[2]  += xv * w0.z;  acc[3]  += xv * w0.w;
            acc[4]  += xv * w1.x;  acc[5]  += xv * w1.y;
            acc[6]  += xv * w1.z;  acc[7]  += xv * w1.w;
            acc[8]  += xv * w2.x;  acc[9]  += xv * w2.y;
            acc[10] += xv * w2.z;  acc[11] += xv * w2.w;
            acc[12] += xv * w3.x;  acc[13] += xv * w3.y;
            acc[14] += xv * w3.z;  acc[15] += xv * w3.w;
        }
        #pragma unroll
        for (int o = 0; o < 16; o++) {
            float y = acc[o];
            y = (y > 0.f) ? y : 0.01f * y;
            z += y * Wts[c * 16 + o];
        }
    }
    g_z[n] = z * g_outnorm[n];
}

// ---------------- layer-3 scalar segment-sum + output ----------------
// out[n] = in[n] * sum over in-edges of z[src] + c0

__global__ void k_spmm_z(float* __restrict__ out) {
    int gtid = blockIdx.x * blockDim.x + threadIdx.x;
    int n = gtid >> 5;
    int lane = gtid & 31;
    if (n >= NN) return;
    int beg = g_rowptr[n];
    int end = g_rowptr[n + 1];
    float s = 0.f;
    for (int e = beg + lane; e < end; e += 32) {
        s += g_z[g_col[e]];
    }
    #pragma unroll
    for (int off = 16; off > 0; off >>= 1)
        s += __shfl_xor_sync(0xffffffffu, s, off);
    if (lane == 0) out[n] = g_innorm[n] * s + g_c0[0];
}

// ---------------- launch ----------------

extern "C" void kernel_launch(void* const* d_in, const int* in_sizes, int n_in,
                              void* d_out, int out_size) {
    const float* weight = (const float*)d_in[0];
    const int*   src    = (const int*)d_in[1];
    const int*   dst    = (const int*)d_in[2];
    const float* W_in   = (const float*)d_in[3];
    const float* b_in   = (const float*)d_in[4];
    const float* Wc     = (const float*)d_in[5];   // [3,64,64]
    const float* bc     = (const float*)d_in[6];   // [3,64]
    const float* W_pred = (const float*)d_in[7];   // [64]
    const float* b_pred = (const float*)d_in[8];   // [1]
    float* out = (float*)d_out;

    const int TB = 256;
    // graph preprocessing (k_fill also push-aggregates layer-1 scalars)
    k_zero<<<(NN + TB - 1) / TB, TB>>>();
    k_degree<<<(EE + TB - 1) / TB, TB>>>(src, dst);
    k_norm<<<(NN + TB - 1) / TB, TB>>>(weight);
    k_scan1<<<NB_SCAN, 256>>>();
    k_scan2<<<1, 512>>>();
    k_scan3<<<NB_SCAN, 256>>>();
    k_fill<<<(EE + NN + TB - 1) / TB, TB>>>(src, dst);

    // tiny parameter transforms
    k_uvwt<<<1, 192>>>(W_in, b_in, Wc, bc, W_pred, b_pred);

    // layer 1 features (closed form from pushed scalars)
    k_s1<<<(NN * 8 + TB - 1) / TB, TB>>>(bc);

    // layer 2: the single vector SpMM + dense (with layer-3 collapse into z)
    k_spmm16<<<(NN * 16 + TB - 1) / TB, TB>>>();
    k_dense_z<<<(NN + 127) / 128, 128>>>(Wc + DD * DD, bc + DD);

    // layer 3: scalar segment-sum of z + output
    k_spmm_z<<<(NN * 32 + TB - 1) / TB, TB>>>(out);
}

// round 11
// speedup vs baseline: 1.7633x; 1.0481x over previous
#include <cuda_runtime.h>
#include <cuda_fp16.h>

// Problem constants (fixed shapes per reference)
#define NN 100000
#define EE 3200000
#define DD 64
#define NB_SCAN ((NN + 255) / 256)   // 391 blocks for scan

// ---------------- static device scratch (no runtime allocation) ----------------
static __device__ int     g_outcnt[NN];
static __device__ int     g_incnt[NN];
static __device__ float   g_outnorm[NN];
static __device__ float   g_innorm[NN];
static __device__ int     g_rowptr[NN + 1];
static __device__ int     g_cursor[NN];
static __device__ int     g_col[EE];         // CSR WITHOUT self loops
static __device__ float2  g_p2[NN];          // (w*out_norm, out_norm)
static __device__ float2  g_ac2[NN];         // pushed (a, c) excluding self
static __device__ float   g_u[DD];           // W_in @ Wc0
static __device__ float   g_v[DD];           // b_in @ Wc0
static __device__ float   g_wt[DD];          // Wc2 @ Wp  (layer-3 collapse vector)
static __device__ float   g_c0[1];           // bc2 . Wp + bp
static __device__ __half2 g_s16[NN * 32];    // fp16 scaled features s1, linear [n][64]
static __device__ uint2   g_aggh[NN * 16];   // fp16 aggregation output (packed half2 x4)
static __device__ float   g_z[NN];           // scalar z = s2 . wt
static __device__ int     g_bsums[512];      // scan block sums

// ---------------- helpers (register bit-ops; proven clean) ----------------

__device__ __forceinline__ float2 u32_to_f2(unsigned u) {
    __half2 h = __halves2half2(__ushort_as_half((unsigned short)(u & 0xffffu)),
                               __ushort_as_half((unsigned short)(u >> 16)));
    return __half22float2(h);
}

__device__ __forceinline__ unsigned f2_to_u32(float x, float y) {
    return (unsigned)__half_as_ushort(__float2half_rn(x)) |
           ((unsigned)__half_as_ushort(__float2half_rn(y)) << 16);
}

// ---------------- graph preprocessing ----------------

__global__ void k_zero() {
    int n = blockIdx.x * blockDim.x + threadIdx.x;
    if (n < NN) {
        g_outcnt[n] = 0; g_incnt[n] = 0;
        g_ac2[n] = make_float2(0.f, 0.f);
    }
}

// 4 edges per thread (EE % 4 == 0)
__global__ void k_degree(const int* __restrict__ src, const int* __restrict__ dst) {
    int i = blockIdx.x * blockDim.x + threadIdx.x;
    if (i < EE / 4) {
        int4 s4 = reinterpret_cast<const int4*>(src)[i];
        int4 d4 = reinterpret_cast<const int4*>(dst)[i];
        atomicAdd(&g_outcnt[s4.x], 1);
        atomicAdd(&g_outcnt[s4.y], 1);
        atomicAdd(&g_outcnt[s4.z], 1);
        atomicAdd(&g_outcnt[s4.w], 1);
        atomicAdd(&g_incnt[d4.x], 1);
        atomicAdd(&g_incnt[d4.y], 1);
        atomicAdd(&g_incnt[d4.z], 1);
        atomicAdd(&g_incnt[d4.w], 1);
    }
}

// norms + p2; last block does the tiny parameter transforms
__global__ void k_norm_uvwt(const float* __restrict__ weight,
                            const float* __restrict__ Win,
                            const float* __restrict__ bin,
                            const float* __restrict__ Wc,
                            const float* __restrict__ bc,
                            const float* __restrict__ Wp,
                            const float* __restrict__ bp) {
    int t = threadIdx.x;
    if (blockIdx.x == gridDim.x - 1) {
        if (t < DD) {
            float u = 0.f, v = 0.f;
            #pragma unroll
            for (int k = 0; k < DD; k++) {
                float w = Wc[k * DD + t];
                u += Win[k] * w;
                v += bin[k] * w;
            }
            g_u[t] = u;
            g_v[t] = v;
        } else if (t < 2 * DD) {
            int j = t - DD;
            float s = 0.f;
            #pragma unroll
            for (int n = 0; n < DD; n++)
                s += Wc[2 * DD * DD + j * DD + n] * Wp[n];
            g_wt[j] = s;
        } else if (t == 2 * DD) {
            float s = 0.f;
            for (int n = 0; n < DD; n++)
                s += bc[2 * DD + n] * Wp[n];
            g_c0[0] = s + bp[0];
        }
        return;
    }
    int n = blockIdx.x * 256 + t;
    if (n < NN) {
        float on = rsqrtf((float)(g_outcnt[n] + 1));   // +1 self loop => always >= 1
        float in = rsqrtf((float)(g_incnt[n] + 1));
        g_outnorm[n] = on;
        g_innorm[n]  = in;
        g_p2[n] = make_float2(weight[n] * on, on);
    }
}

// exclusive scan of incnt (self loops NOT in CSR)
__global__ void k_scan1() {
    __shared__ int s[256];
    int t = threadIdx.x;
    int n = blockIdx.x * 256 + t;
    int v = (n < NN) ? g_incnt[n] : 0;
    s[t] = v;
    __syncthreads();
    for (int off = 1; off < 256; off <<= 1) {
        int tmp = (t >= off) ? s[t - off] : 0;
        __syncthreads();
        s[t] += tmp;
        __syncthreads();
    }
    if (t == 255) g_bsums[blockIdx.x] = s[255];
}

__global__ void k_scan2() {
    __shared__ int s[512];
    int t = threadIdx.x;
    int v = (t < NB_SCAN) ? g_bsums[t] : 0;
    s[t] = v;
    __syncthreads();
    for (int off = 1; off < 512; off <<= 1) {
        int tmp = (t >= off) ? s[t - off] : 0;
        __syncthreads();
        s[t] += tmp;
        __syncthreads();
    }
    if (t < NB_SCAN) g_bsums[t] = s[t] - v;   // exclusive block offsets
}

__global__ void k_scan3() {
    __shared__ int s[256];
    int t = threadIdx.x;
    int n = blockIdx.x * 256 + t;
    int v = (n < NN) ? g_incnt[n] : 0;
    s[t] = v;
    __syncthreads();
    for (int off = 1; off < 256; off <<= 1) {
        int tmp = (t >= off) ? s[t - off] : 0;
        __syncthreads();
        s[t] += tmp;
        __syncthreads();
    }
    if (n < NN) {
        int start = g_bsums[blockIdx.x] + s[t] - v;
        g_rowptr[n] = start;
        g_cursor[n] = start;
    }
    if (blockIdx.x == 0 && t == 0) g_rowptr[NN] = EE;
}

// CSR fill + fused push of layer-1 scalars; 4 edges per thread, no self loops
__global__ void k_fill(const int* __restrict__ src, const int* __restrict__ dst) {
    int i = blockIdx.x * blockDim.x + threadIdx.x;
    if (i < EE / 4) {
        int4 s4 = reinterpret_cast<const int4*>(src)[i];
        int4 d4 = reinterpret_cast<const int4*>(dst)[i];

        int pos0 = atomicAdd(&g_cursor[d4.x], 1);
        g_col[pos0] = s4.x;
        float2 p0 = g_p2[s4.x];
        atomicAdd(&g_ac2[d4.x].x, p0.x);
        atomicAdd(&g_ac2[d4.x].y, p0.y);

        int pos1 = atomicAdd(&g_cursor[d4.y], 1);
        g_col[pos1] = s4.y;
        float2 p1 = g_p2[s4.y];
        atomicAdd(&g_ac2[d4.y].x, p1.x);
        atomicAdd(&g_ac2[d4.y].y, p1.y);

        int pos2 = atomicAdd(&g_cursor[d4.z], 1);
        g_col[pos2] = s4.z;
        float2 p2 = g_p2[s4.z];
        atomicAdd(&g_ac2[d4.z].x, p2.x);
        atomicAdd(&g_ac2[d4.z].y, p2.y);

        int pos3 = atomicAdd(&g_cursor[d4.w], 1);
        g_col[pos3] = s4.w;
        float2 p3 = g_p2[s4.w];
        atomicAdd(&g_ac2[d4.w].x, p3.x);
        atomicAdd(&g_ac2[d4.w].y, p3.y);
    }
}

// s1[n] = leaky( ((a+self)*in)*u + ((c+self)*in)*v + bc0 ) * on   -> fp16
__global__ void k_s1(const float* __restrict__ bc0) {
    int idx = blockIdx.x * blockDim.x + threadIdx.x;   // NN * 8 groups of 8 dims
    if (idx >= NN * 8) return;
    int n = idx >> 3;
    int j0 = (idx & 7) * 8;
    float2 ac = g_ac2[n];
    float2 ps = g_p2[n];                               // self-loop contribution
    float in = g_innorm[n];
    float on = g_outnorm[n];
    float alpha = (ac.x + ps.x) * in;
    float gamma = (ac.y + ps.y) * in;
    __half2 h[4];
    #pragma unroll
    for (int p = 0; p < 4; p++) {
        int j = j0 + p * 2;
        float y0 = alpha * g_u[j]     + gamma * g_v[j]     + bc0[j];
        float y1 = alpha * g_u[j + 1] + gamma * g_v[j + 1] + bc0[j + 1];
        y0 = (y0 > 0.f) ? y0 : 0.01f * y0;
        y1 = (y1 > 0.f) ? y1 : 0.01f * y1;
        h[p] = __floats2half2_rn(y0 * on, y1 * on);
    }
    *reinterpret_cast<uint4*>(&g_s16[n * 32 + (idx & 7) * 4]) =
        *reinterpret_cast<uint4*>(h);
}

// ---------------- SpMM: 2 nodes per warp, 16 lanes each, 8B/lane gathers ----------------
// fp32 accumulate, fp16 (packed) store; self contribution added directly.

__global__ void k_spmm16() {
    int gtid = blockIdx.x * blockDim.x + threadIdx.x;
    int n = gtid >> 4;      // node
    int s = gtid & 15;      // sublane: dims 4s..4s+3
    bool valid = (n < NN);
    int beg = valid ? g_rowptr[n] : 0;
    int end = valid ? g_rowptr[n + 1] : 0;
    int nb = (end - beg + 15) >> 4;
    int nbo = __shfl_xor_sync(0xffffffffu, nb, 16);
    int nbm = max(nb, nbo);                           // warp-uniform outer bound
    const uint2* sp = reinterpret_cast<const uint2*>(g_s16);
    // self contribution (agg includes own features via self loop)
    float a0 = 0.f, a1 = 0.f, a2 = 0.f, a3 = 0.f;
    if (valid) {
        uint2 v = sp[n * 16 + s];
        float2 f0 = u32_to_f2(v.x);
        float2 f1 = u32_to_f2(v.y);
        a0 = f0.x; a1 = f0.y; a2 = f1.x; a3 = f1.y;
    }
    for (int it = 0; it < nbm; it++) {
        int e = beg + (it << 4);
        int cnt = min(16, end - e);                   // may be <= 0 for finished half
        int idx = (s < cnt) ? g_col[e + s] : 0;
        int cnto = __shfl_xor_sync(0xffffffffu, cnt, 16);
        if (min(cnt, cnto) == 16) {
            #pragma unroll
            for (int j = 0; j < 16; j++) {
                int srcn = __shfl_sync(0xffffffffu, idx, j, 16);
                uint2 v = sp[srcn * 16 + s];
                float2 f0 = u32_to_f2(v.x);
                float2 f1 = u32_to_f2(v.y);
                a0 += f0.x; a1 += f0.y;
                a2 += f1.x; a3 += f1.y;
            }
        } else {
            int cntm = max(cnt, cnto);
            for (int j = 0; j < cntm; j++) {
                int srcn = __shfl_sync(0xffffffffu, idx, j, 16);
                if (j < cnt) {
                    uint2 v = sp[srcn * 16 + s];
                    float2 f0 = u32_to_f2(v.x);
                    float2 f1 = u32_to_f2(v.y);
                    a0 += f0.x; a1 += f0.y;
                    a2 += f1.x; a3 += f1.y;
                }
            }
        }
    }
    if (valid)
        g_aggh[n * 16 + s] = make_uint2(f2_to_u32(a0, a1), f2_to_u32(a2, a3));
}

// ---------------- dense layer 2 + layer-3 collapse (proven FFMA pattern) ----------------
// x = aggh[n]*in; y = x@Wc1 + bc1; z[n] = on * sum_o leaky(y_o) * wt_o

__global__ void k_dense_z(const float* __restrict__ W,
                          const float* __restrict__ b) {
    __shared__ float Ws[DD * DD];
    __shared__ float Bs[DD];
    __shared__ float Wts[DD];
    int t = threadIdx.x;
    {
        const float4* w4 = reinterpret_cast<const float4*>(W);
        float4* s4 = reinterpret_cast<float4*>(Ws);
        #pragma unroll
        for (int i = 0; i < 8; i++) s4[t + i * 128] = w4[t + i * 128];
        if (t < DD) { Bs[t] = b[t]; Wts[t] = g_wt[t]; }
    }
    __syncthreads();

    int n = blockIdx.x * blockDim.x + t;
    if (n >= NN) return;

    float x[DD];
    {
        float sc = g_innorm[n];
        const uint4* ap = reinterpret_cast<const uint4*>(g_aggh) + n * 8;
        #pragma unroll
        for (int i = 0; i < 8; i++) {       // uint4 = 8 halfs = dims 8i..8i+7
            uint4 v = ap[i];
            float2 f0 = u32_to_f2(v.x);
            float2 f1 = u32_to_f2(v.y);
            float2 f2 = u32_to_f2(v.z);
            float2 f3 = u32_to_f2(v.w);
            x[i * 8 + 0] = f0.x * sc;  x[i * 8 + 1] = f0.y * sc;
            x[i * 8 + 2] = f1.x * sc;  x[i * 8 + 3] = f1.y * sc;
            x[i * 8 + 4] = f2.x * sc;  x[i * 8 + 5] = f2.y * sc;
            x[i * 8 + 6] = f3.x * sc;  x[i * 8 + 7] = f3.y * sc;
        }
    }

    float z = 0.f;
    #pragma unroll
    for (int c = 0; c < 4; c++) {
        float acc[16];
        #pragma unroll
        for (int o = 0; o < 16; o++) acc[o] = Bs[c * 16 + o];
        #pragma unroll
        for (int k = 0; k < DD; k++) {
            float xv = x[k];
            const float4* wr = reinterpret_cast<const float4*>(&Ws[k * DD + c * 16]);
            float4 w0 = wr[0], w1 = wr[1], w2 = wr[2], w3 = wr[3];
            acc[0]  += xv * w0.x;  acc[1]  += xv * w0.y;
            acc[2]  += xv * w0.z;  acc[3]  += xv * w0.w;
            acc[4]  += xv * w1.x;  acc[5]  += xv * w1.y;
            acc[6]  += xv * w1.z;  acc[7]  += xv * w1.w;
            acc[8]  += xv * w2.x;  acc[9]  += xv * w2.y;
            acc[10] += xv * w2.z;  acc[11] += xv * w2.w;
            acc[12] += xv * w3.x;  acc[13] += xv * w3.y;
            acc[14] += xv * w3.z;  acc[15] += xv * w3.w;
        }
        #pragma unroll
        for (int o = 0; o < 16; o++) {
            float y = acc[o];
            y = (y > 0.f) ? y : 0.01f * y;
            z += y * Wts[c * 16 + o];
        }
    }
    g_z[n] = z * g_outnorm[n];
}

// ---------------- layer-3 scalar segment-sum + output ----------------
// out[n] = in[n] * ( sum over in-edges of z[src] + z[n] ) + c0

__global__ void k_spmm_z(float* __restrict__ out) {
    int gtid = blockIdx.x * blockDim.x + threadIdx.x;
    int n = gtid >> 5;
    int lane = gtid & 31;
    if (n >= NN) return;
    int beg = g_rowptr[n];
    int end = g_rowptr[n + 1];
    float s = 0.f;
    for (int e = beg + lane; e < end; e += 32) {
        s += g_z[g_col[e]];
    }
    #pragma unroll
    for (int off = 16; off > 0; off >>= 1)
        s += __shfl_xor_sync(0xffffffffu, s, off);
    if (lane == 0) out[n] = g_innorm[n] * (s + g_z[n]) + g_c0[0];
}

// ---------------- launch ----------------

extern "C" void kernel_launch(void* const* d_in, const int* in_sizes, int n_in,
                              void* d_out, int out_size) {
    const float* weight = (const float*)d_in[0];
    const int*   src    = (const int*)d_in[1];
    const int*   dst    = (const int*)d_in[2];
    const float* W_in   = (const float*)d_in[3];
    const float* b_in   = (const float*)d_in[4];
    const float* Wc     = (const float*)d_in[5];   // [3,64,64]
    const float* bc     = (const float*)d_in[6];   // [3,64]
    const float* W_pred = (const float*)d_in[7];   // [64]
    const float* b_pred = (const float*)d_in[8];   // [1]
    float* out = (float*)d_out;

    const int TB = 256;
    // graph preprocessing (k_fill also push-aggregates layer-1 scalars)
    k_zero<<<(NN + TB - 1) / TB, TB>>>();
    k_degree<<<(EE / 4 + TB - 1) / TB, TB>>>(src, dst);
    k_norm_uvwt<<<NB_SCAN + 1, 256>>>(weight, W_in, b_in, Wc, bc, W_pred, b_pred);
    k_scan1<<<NB_SCAN, 256>>>();
    k_scan2<<<1, 512>>>();
    k_scan3<<<NB_SCAN, 256>>>();
    k_fill<<<(EE / 4 + TB - 1) / TB, TB>>>(src, dst);

    // layer 1 features (closed form from pushed scalars + self)
    k_s1<<<(NN * 8 + TB - 1) / TB, TB>>>(bc);

    // layer 2: the single vector SpMM + dense (with layer-3 collapse into z)
    k_spmm16<<<(NN * 16 + TB - 1) / TB, TB>>>();
    k_dense_z<<<(NN + 127) / 128, 128>>>(Wc + DD * DD, bc + DD);

    // layer 3: scalar segment-sum of z + output
    k_spmm_z<<<(NN * 32 + TB - 1) / TB, TB>>>(out);
}